// round 1
// baseline (speedup 1.0000x reference)
#include <cuda_runtime.h>
#include <cuda_bf16.h>
#include <math.h>

// ---------------------------------------------------------------------------
// Problem constants: B=2, S=2048, D=1024, H=16, dh=64
// ---------------------------------------------------------------------------
#define B_  2
#define S_  2048
#define D_  1024
#define H_  16
#define DH_ 64
#define M_TOK (B_ * S_)          // 4096 tokens

// Scratch (no cudaMalloc allowed): qkv [4096,3072], attn out [4096,1024]
__device__ float g_qkv[M_TOK * 3 * D_];
__device__ float g_attn[M_TOK * D_];

// ---------------------------------------------------------------------------
// SIMT fp32 SGEMM: C[M,N] = A[M,K] @ B[K,N], all row-major.
// BM=BN=128, BK=16, 256 threads, 8x8 microtile. Dims assumed multiples.
// ---------------------------------------------------------------------------
#define BM 128
#define BN 128
#define BK 16
#define TM 8
#define TN 8

__global__ __launch_bounds__(256) void sgemm_kernel(
    const float* __restrict__ A, const float* __restrict__ Bm,
    float* __restrict__ C, int M, int N, int K)
{
    __shared__ float As[BK][BM];
    __shared__ float Bs[BK][BN];

    const int tid = threadIdx.x;
    const int bm = blockIdx.y * BM;
    const int bn = blockIdx.x * BN;

    const int tr = (tid / (BN / TN)) * TM;   // 0..120
    const int tc = (tid % (BN / TN)) * TN;   // 0..120

    float acc[TM][TN];
#pragma unroll
    for (int i = 0; i < TM; i++)
#pragma unroll
        for (int j = 0; j < TN; j++) acc[i][j] = 0.f;

    for (int k0 = 0; k0 < K; k0 += BK) {
        // Load A tile (BM x BK) transposed into As[BK][BM]
#pragma unroll
        for (int it = 0; it < (BM * BK) / (256 * 4); ++it) {
            int idx = tid + it * 256;            // float4 index
            int r   = idx / (BK / 4);            // 0..127
            int c4  = idx % (BK / 4);            // 0..3
            float4 v = *(const float4*)&A[(size_t)(bm + r) * K + k0 + c4 * 4];
            As[c4 * 4 + 0][r] = v.x;
            As[c4 * 4 + 1][r] = v.y;
            As[c4 * 4 + 2][r] = v.z;
            As[c4 * 4 + 3][r] = v.w;
        }
        // Load B tile (BK x BN)
#pragma unroll
        for (int it = 0; it < (BK * BN) / (256 * 4); ++it) {
            int idx = tid + it * 256;
            int r   = idx / (BN / 4);            // 0..15
            int c4  = idx % (BN / 4);            // 0..31
            *(float4*)&Bs[r][c4 * 4] =
                *(const float4*)&Bm[(size_t)(k0 + r) * N + bn + c4 * 4];
        }
        __syncthreads();

#pragma unroll
        for (int k = 0; k < BK; ++k) {
            float a[TM], b[TN];
#pragma unroll
            for (int i = 0; i < TM; i++) a[i] = As[k][tr + i];
#pragma unroll
            for (int j = 0; j < TN; j++) b[j] = Bs[k][tc + j];
#pragma unroll
            for (int i = 0; i < TM; i++)
#pragma unroll
                for (int j = 0; j < TN; j++) acc[i][j] += a[i] * b[j];
        }
        __syncthreads();
    }

#pragma unroll
    for (int i = 0; i < TM; i++)
#pragma unroll
        for (int j = 0; j < TN; j += 4) {
            float4 v = make_float4(acc[i][j], acc[i][j + 1], acc[i][j + 2], acc[i][j + 3]);
            *(float4*)&C[(size_t)(bm + tr + i) * N + bn + tc + j] = v;
        }
}

// ---------------------------------------------------------------------------
// Flash attention, fp32. One block = (b, h, 64-query tile). 256 threads:
// thread (row = tid>>2, sub = tid&3). Each thread owns 16 key-cols for the
// score phase and 16 dh-cols of the output accumulator.
// Smem tiles padded to stride 68 floats (bank-conflict-free float4 access).
// ---------------------------------------------------------------------------
#define SD 68
#define ATTN_SMEM (4 * 64 * SD * sizeof(float))   // 69632 bytes
#define NEG_INF_F (-1e30f)

__global__ __launch_bounds__(256) void attn_kernel(
    const float* __restrict__ qkv, float* __restrict__ out)
{
    const int qt  = blockIdx.x;      // query tile (0..31)
    const int h   = blockIdx.y;      // head
    const int b   = blockIdx.z;      // batch
    const int tid = threadIdx.x;
    const int row = tid >> 2;        // 0..63
    const int sub = tid & 3;         // 0..3

    extern __shared__ float sm[];
    float* Qs = sm;
    float* Ks = sm + 64 * SD;
    float* Vs = sm + 2 * 64 * SD;
    float* Ps = sm + 3 * 64 * SD;

    const float scale = 0.125f;                       // dh^-0.5 = 1/8
    const size_t base = (size_t)b * S_ * 3 * D_;

    // Load Q tile: 64x64 floats, 4 float4 per thread
    for (int i = tid; i < 64 * 16; i += 256) {
        int r = i >> 4, c4 = i & 15;
        *(float4*)&Qs[r * SD + c4 * 4] =
            *(const float4*)&qkv[base + (size_t)(qt * 64 + r) * 3 * D_ + h * DH_ + c4 * 4];
    }

    float m = NEG_INF_F, l = 0.f;
    float o[16];
#pragma unroll
    for (int j = 0; j < 16; j++) o[j] = 0.f;

    const int n_tiles = qt + 1;      // causal: only key tiles <= query tile
    for (int kt = 0; kt < n_tiles; ++kt) {
        __syncthreads();   // Qs visible (1st iter) / protect Ks,Vs,Ps reuse
        for (int i = tid; i < 64 * 16; i += 256) {
            int r = i >> 4, c4 = i & 15;
            size_t rb = base + (size_t)(kt * 64 + r) * 3 * D_ + h * DH_ + c4 * 4;
            *(float4*)&Ks[r * SD + c4 * 4] = *(const float4*)&qkv[rb + D_];
            *(float4*)&Vs[r * SD + c4 * 4] = *(const float4*)&qkv[rb + 2 * D_];
        }
        __syncthreads();

        // ---- scores: s[j] = Q[row,:] . K[sub*16+j,:] ----
        float s[16];
#pragma unroll
        for (int j = 0; j < 16; j++) s[j] = 0.f;
#pragma unroll
        for (int k = 0; k < DH_; k += 4) {
            float4 q4 = *(float4*)&Qs[row * SD + k];
#pragma unroll
            for (int j = 0; j < 16; j++) {
                float4 k4 = *(float4*)&Ks[(sub * 16 + j) * SD + k];
                s[j] += q4.x * k4.x + q4.y * k4.y + q4.z * k4.z + q4.w * k4.w;
            }
        }

        // ---- causal mask + scale + local max ----
        const int gq = qt * 64 + row;
        float mloc = NEG_INF_F;
#pragma unroll
        for (int j = 0; j < 16; j++) {
            int gk = kt * 64 + sub * 16 + j;
            s[j] = (gk <= gq) ? s[j] * scale : NEG_INF_F;
            mloc = fmaxf(mloc, s[j]);
        }
        // reduce max over the 4 subs (consecutive lanes)
        mloc = fmaxf(mloc, __shfl_xor_sync(0xffffffffu, mloc, 1));
        mloc = fmaxf(mloc, __shfl_xor_sync(0xffffffffu, mloc, 2));
        const float mnew = fmaxf(m, mloc);   // always finite (diagonal valid)
        const float corr = __expf(m - mnew);

        // ---- p = exp(s - mnew), row sum ----
        float p[16], psum = 0.f;
#pragma unroll
        for (int j = 0; j < 16; j++) { p[j] = __expf(s[j] - mnew); psum += p[j]; }
        psum += __shfl_xor_sync(0xffffffffu, psum, 1);
        psum += __shfl_xor_sync(0xffffffffu, psum, 2);
        l = l * corr + psum;
        m = mnew;
#pragma unroll
        for (int j = 0; j < 16; j++) o[j] *= corr;

        // stage P to smem so every thread can read the full 64 key-cols
#pragma unroll
        for (int j = 0; j < 16; j += 4) {
            float4 v = make_float4(p[j], p[j + 1], p[j + 2], p[j + 3]);
            *(float4*)&Ps[row * SD + sub * 16 + j] = v;
        }
        __syncthreads();

        // ---- O[row, sub*16+j] += sum_c P[row,c] * V[c, sub*16+j] ----
#pragma unroll
        for (int c = 0; c < 64; c += 4) {
            float4 p4 = *(float4*)&Ps[row * SD + c];
            const float pw[4] = {p4.x, p4.y, p4.z, p4.w};
#pragma unroll
            for (int jj = 0; jj < 4; jj++) {
                float pv = pw[jj];
#pragma unroll
                for (int j = 0; j < 16; j += 4) {
                    float4 v4 = *(float4*)&Vs[(c + jj) * SD + sub * 16 + j];
                    o[j]     += pv * v4.x;
                    o[j + 1] += pv * v4.y;
                    o[j + 2] += pv * v4.z;
                    o[j + 3] += pv * v4.w;
                }
            }
        }
    }

    // epilogue: normalized O back to [b, s, h*dh + d] layout (ready for @ w_out)
    const float inv = 1.f / l;
    const size_t obase = ((size_t)(b * S_ + qt * 64 + row)) * D_ + h * DH_ + sub * 16;
#pragma unroll
    for (int j = 0; j < 16; j += 4) {
        float4 v = make_float4(o[j] * inv, o[j + 1] * inv, o[j + 2] * inv, o[j + 3] * inv);
        *(float4*)&out[obase + j] = v;
    }
}

// ---------------------------------------------------------------------------
// Launch
// ---------------------------------------------------------------------------
extern "C" void kernel_launch(void* const* d_in, const int* in_sizes, int n_in,
                              void* d_out, int out_size)
{
    const float* x     = (const float*)d_in[0];   // [B,S,D] = [4096,1024]
    const float* w_qkv = (const float*)d_in[1];   // [1024,3072]
    const float* w_out = (const float*)d_in[2];   // [1024,1024]
    float* out = (float*)d_out;                   // [4096,1024]

    float* qkv = nullptr;
    float* attn = nullptr;
    cudaGetSymbolAddress((void**)&qkv, g_qkv);
    cudaGetSymbolAddress((void**)&attn, g_attn);

    // 1) QKV projection: [4096,1024] @ [1024,3072]
    {
        dim3 grid(3 * D_ / BN, M_TOK / BM);
        sgemm_kernel<<<grid, 256>>>(x, w_qkv, qkv, M_TOK, 3 * D_, D_);
    }

    // 2) Flash attention
    {
        cudaFuncSetAttribute(attn_kernel,
                             cudaFuncAttributeMaxDynamicSharedMemorySize,
                             (int)ATTN_SMEM);
        dim3 grid(S_ / 64, H_, B_);
        attn_kernel<<<grid, 256, ATTN_SMEM>>>(qkv, attn);
    }

    // 3) Output projection: [4096,1024] @ [1024,1024]
    {
        dim3 grid(D_ / BN, M_TOK / BM);
        sgemm_kernel<<<grid, 256>>>(attn, w_out, out, M_TOK, D_, D_);
    }
}

// round 2
// speedup vs baseline: 3.1606x; 3.1606x over previous
#include <cuda_runtime.h>
#include <cuda_bf16.h>
#include <math.h>
#include <stdint.h>

// ---------------------------------------------------------------------------
// Problem constants: B=2, S=2048, D=1024, H=16, dh=64
// ---------------------------------------------------------------------------
#define B_  2
#define S_  2048
#define D_  1024
#define H_  16
#define DH_ 64
#define M_TOK (B_ * S_)          // 4096 tokens

// Scratch (no cudaMalloc allowed): qkv [4096,3072], attn out [4096,1024]
__device__ float g_qkv[M_TOK * 3 * D_];
__device__ float g_attn[M_TOK * D_];

// ---------------------------------------------------------------------------
// Helpers: cp.async
// ---------------------------------------------------------------------------
__device__ __forceinline__ uint32_t smem_u32(const void* p) {
    return (uint32_t)__cvta_generic_to_shared(p);
}
__device__ __forceinline__ void cp_async16(uint32_t dst, const void* src) {
    asm volatile("cp.async.cg.shared.global [%0], [%1], 16;\n" :: "r"(dst), "l"(src));
}
__device__ __forceinline__ void cp_commit() {
    asm volatile("cp.async.commit_group;\n" ::: "memory");
}
__device__ __forceinline__ void cp_wait0() {
    asm volatile("cp.async.wait_group 0;\n" ::: "memory");
}
__device__ __forceinline__ void cp_wait1() {
    asm volatile("cp.async.wait_group 1;\n" ::: "memory");
}

// ---------------------------------------------------------------------------
// SIMT fp32 SGEMM: C[M,N] = A[M,K] @ B[K,N], all row-major.
// BM=BN=128, BK=16, 256 threads, 8x8 microtile. (unchanged from R1)
// ---------------------------------------------------------------------------
#define BM 128
#define BN 128
#define BK 16
#define TM 8
#define TN 8

__global__ __launch_bounds__(256) void sgemm_kernel(
    const float* __restrict__ A, const float* __restrict__ Bm,
    float* __restrict__ C, int M, int N, int K)
{
    __shared__ float As[BK][BM];
    __shared__ float Bs[BK][BN];

    const int tid = threadIdx.x;
    const int bm = blockIdx.y * BM;
    const int bn = blockIdx.x * BN;

    const int tr = (tid / (BN / TN)) * TM;
    const int tc = (tid % (BN / TN)) * TN;

    float acc[TM][TN];
#pragma unroll
    for (int i = 0; i < TM; i++)
#pragma unroll
        for (int j = 0; j < TN; j++) acc[i][j] = 0.f;

    for (int k0 = 0; k0 < K; k0 += BK) {
#pragma unroll
        for (int it = 0; it < (BM * BK) / (256 * 4); ++it) {
            int idx = tid + it * 256;
            int r   = idx / (BK / 4);
            int c4  = idx % (BK / 4);
            float4 v = *(const float4*)&A[(size_t)(bm + r) * K + k0 + c4 * 4];
            As[c4 * 4 + 0][r] = v.x;
            As[c4 * 4 + 1][r] = v.y;
            As[c4 * 4 + 2][r] = v.z;
            As[c4 * 4 + 3][r] = v.w;
        }
#pragma unroll
        for (int it = 0; it < (BK * BN) / (256 * 4); ++it) {
            int idx = tid + it * 256;
            int r   = idx / (BN / 4);
            int c4  = idx % (BN / 4);
            *(float4*)&Bs[r][c4 * 4] =
                *(const float4*)&Bm[(size_t)(k0 + r) * N + bn + c4 * 4];
        }
        __syncthreads();

#pragma unroll
        for (int k = 0; k < BK; ++k) {
            float a[TM], b[TN];
#pragma unroll
            for (int i = 0; i < TM; i++) a[i] = As[k][tr + i];
#pragma unroll
            for (int j = 0; j < TN; j++) b[j] = Bs[k][tc + j];
#pragma unroll
            for (int i = 0; i < TM; i++)
#pragma unroll
                for (int j = 0; j < TN; j++) acc[i][j] += a[i] * b[j];
        }
        __syncthreads();
    }

#pragma unroll
    for (int i = 0; i < TM; i++)
#pragma unroll
        for (int j = 0; j < TN; j += 4) {
            float4 v = make_float4(acc[i][j], acc[i][j + 1], acc[i][j + 2], acc[i][j + 3]);
            *(float4*)&C[(size_t)(bm + tr + i) * N + bn + tc + j] = v;
        }
}

// ---------------------------------------------------------------------------
// Flash attention v2 (fp32, register-blocked 4x4, cp.async double buffering).
// One block = (b, h, 64-query tile). 256 threads.
// Thread (rg = tid>>4, cg = tid&15): owns a 4x4 microtile:
//   QK phase: rows tr..tr+3 (tr = rg*4), cols {cg + 16*j}, j=0..3
//   PV phase: rows tr..tr+3, dh-cols cg*4..cg*4+3
// Smem: Qs[64][68], Ks[2][64][68], Vs[2][64][68], Pt[64][68] (Pt row = key)
// ---------------------------------------------------------------------------
#define SD 68
#define ATTN_SMEM (6 * 64 * SD * sizeof(float))   // 104448 bytes
#define NEG_INF_F (-1e30f)

__global__ __launch_bounds__(256, 2) void attn_kernel(
    const float* __restrict__ qkv, float* __restrict__ out)
{
    const int qt  = (int)gridDim.x - 1 - (int)blockIdx.x;  // heavy blocks first
    const int h   = blockIdx.y;
    const int b   = blockIdx.z;
    const int tid = threadIdx.x;
    const int rg  = tid >> 4;
    const int cg  = tid & 15;
    const int tr  = rg * 4;

    extern __shared__ float sm[];
    float* Qs = sm;                    // [64][SD]
    float* Ks = sm + 64 * SD;          // [2][64][SD]
    float* Vs = sm + 3 * 64 * SD;      // [2][64][SD]
    float* Pt = sm + 5 * 64 * SD;      // [64][SD]   (row = key idx, col = query idx)

    const float scale = 0.125f;        // dh^-0.5
    const size_t base = (size_t)b * S_ * 3 * D_ + (size_t)h * DH_;

    // --- load Q tile (plain LDG->STS; overlapped with first cp.async) ---
    // Issue K/V tile 0 first so DRAM latency overlaps the Q loads.
    {
        // cp.async K/V for kt = 0 into buffer 0
        for (int i = tid; i < 64 * 16; i += 256) {
            int r = i >> 4, c4 = i & 15;
            size_t g = base + (size_t)(r) * 3 * D_ + c4 * 4;   // kt = 0
            cp_async16(smem_u32(&Ks[(size_t)r * SD + c4 * 4]), &qkv[g + D_]);
            cp_async16(smem_u32(&Vs[(size_t)r * SD + c4 * 4]), &qkv[g + 2 * D_]);
        }
        cp_commit();
        for (int i = tid; i < 64 * 16; i += 256) {
            int r = i >> 4, c4 = i & 15;
            *(float4*)&Qs[(size_t)r * SD + c4 * 4] =
                *(const float4*)&qkv[base + (size_t)(qt * 64 + r) * 3 * D_ + c4 * 4];
        }
    }

    float m[4], l[4], o[4][4];
#pragma unroll
    for (int i = 0; i < 4; i++) {
        m[i] = NEG_INF_F; l[i] = 0.f;
#pragma unroll
        for (int j = 0; j < 4; j++) o[i][j] = 0.f;
    }

    const int n_tiles = qt + 1;
    for (int kt = 0; kt < n_tiles; ++kt) {
        const int buf = kt & 1;
        if (kt > 0) __syncthreads();   // everyone done with buf^1 from iter kt-1

        if (kt + 1 < n_tiles) {
            float* Kn = &Ks[(size_t)(buf ^ 1) * 64 * SD];
            float* Vn = &Vs[(size_t)(buf ^ 1) * 64 * SD];
            for (int i = tid; i < 64 * 16; i += 256) {
                int r = i >> 4, c4 = i & 15;
                size_t g = base + (size_t)((kt + 1) * 64 + r) * 3 * D_ + c4 * 4;
                cp_async16(smem_u32(&Kn[(size_t)r * SD + c4 * 4]), &qkv[g + D_]);
                cp_async16(smem_u32(&Vn[(size_t)r * SD + c4 * 4]), &qkv[g + 2 * D_]);
            }
            cp_commit();
            cp_wait1();                // tile kt finished
        } else {
            cp_wait0();
        }
        __syncthreads();               // tile kt visible to all

        const float* Kb = &Ks[(size_t)buf * 64 * SD];
        const float* Vb = &Vs[(size_t)buf * 64 * SD];

        // ---- scores: s[i][j] = Q[tr+i,:] . K[cg+16j,:] ----
        float s[4][4];
#pragma unroll
        for (int i = 0; i < 4; i++)
#pragma unroll
            for (int j = 0; j < 4; j++) s[i][j] = 0.f;

#pragma unroll
        for (int k = 0; k < DH_; k += 4) {
            float4 q4[4];
#pragma unroll
            for (int i = 0; i < 4; i++) q4[i] = *(float4*)&Qs[(size_t)(tr + i) * SD + k];
#pragma unroll
            for (int j = 0; j < 4; j++) {
                float4 k4 = *(const float4*)&Kb[(size_t)(cg + 16 * j) * SD + k];
#pragma unroll
                for (int i = 0; i < 4; i++) {
                    s[i][j] += q4[i].x * k4.x + q4[i].y * k4.y
                             + q4[i].z * k4.z + q4[i].w * k4.w;
                }
            }
        }

        // ---- causal mask + scale + online softmax ----
        const bool interior = (kt < qt);
        float corr[4];
#pragma unroll
        for (int i = 0; i < 4; i++) {
            const int gq = qt * 64 + tr + i;
            float mloc = NEG_INF_F;
#pragma unroll
            for (int j = 0; j < 4; j++) {
                int gk = kt * 64 + cg + 16 * j;
                bool ok = interior || (gk <= gq);
                s[i][j] = ok ? s[i][j] * scale : NEG_INF_F;
                mloc = fmaxf(mloc, s[i][j]);
            }
            mloc = fmaxf(mloc, __shfl_xor_sync(0xffffffffu, mloc, 1));
            mloc = fmaxf(mloc, __shfl_xor_sync(0xffffffffu, mloc, 2));
            mloc = fmaxf(mloc, __shfl_xor_sync(0xffffffffu, mloc, 4));
            mloc = fmaxf(mloc, __shfl_xor_sync(0xffffffffu, mloc, 8));
            const float mnew = fmaxf(m[i], mloc);
            corr[i] = __expf(m[i] - mnew);
            m[i] = mnew;
        }
#pragma unroll
        for (int i = 0; i < 4; i++) {
            float psum = 0.f;
#pragma unroll
            for (int j = 0; j < 4; j++) {
                s[i][j] = __expf(s[i][j] - m[i]);
                psum += s[i][j];
            }
            psum += __shfl_xor_sync(0xffffffffu, psum, 1);
            psum += __shfl_xor_sync(0xffffffffu, psum, 2);
            psum += __shfl_xor_sync(0xffffffffu, psum, 4);
            psum += __shfl_xor_sync(0xffffffffu, psum, 8);
            l[i] = l[i] * corr[i] + psum;
#pragma unroll
            for (int j = 0; j < 4; j++) o[i][j] *= corr[i];
        }

        // ---- stage P transposed: Pt[key][query] ----
#pragma unroll
        for (int j = 0; j < 4; j++) {
            float4 v = make_float4(s[0][j], s[1][j], s[2][j], s[3][j]);
            *(float4*)&Pt[(size_t)(cg + 16 * j) * SD + tr] = v;
        }
        __syncthreads();

        // ---- PV: o[i][j] += sum_c Pt[c][tr+i] * V[c][cg*4+j] ----
#pragma unroll 4
        for (int c = 0; c < 64; ++c) {
            float4 p4 = *(float4*)&Pt[(size_t)c * SD + tr];
            float4 v4 = *(const float4*)&Vb[(size_t)c * SD + cg * 4];
            o[0][0] += p4.x * v4.x; o[0][1] += p4.x * v4.y;
            o[0][2] += p4.x * v4.z; o[0][3] += p4.x * v4.w;
            o[1][0] += p4.y * v4.x; o[1][1] += p4.y * v4.y;
            o[1][2] += p4.y * v4.z; o[1][3] += p4.y * v4.w;
            o[2][0] += p4.z * v4.x; o[2][1] += p4.z * v4.y;
            o[2][2] += p4.z * v4.z; o[2][3] += p4.z * v4.w;
            o[3][0] += p4.w * v4.x; o[3][1] += p4.w * v4.y;
            o[3][2] += p4.w * v4.z; o[3][3] += p4.w * v4.w;
        }
    }

    // ---- epilogue: normalize + store to [b, s, h*dh + d] ----
#pragma unroll
    for (int i = 0; i < 4; i++) {
        const float inv = 1.f / l[i];
        float4 v = make_float4(o[i][0] * inv, o[i][1] * inv,
                               o[i][2] * inv, o[i][3] * inv);
        const size_t ob = ((size_t)(b * S_ + qt * 64 + tr + i)) * D_ + h * DH_ + cg * 4;
        *(float4*)&out[ob] = v;
    }
}

// ---------------------------------------------------------------------------
// Launch
// ---------------------------------------------------------------------------
extern "C" void kernel_launch(void* const* d_in, const int* in_sizes, int n_in,
                              void* d_out, int out_size)
{
    const float* x     = (const float*)d_in[0];   // [4096,1024]
    const float* w_qkv = (const float*)d_in[1];   // [1024,3072]
    const float* w_out = (const float*)d_in[2];   // [1024,1024]
    float* out = (float*)d_out;                   // [4096,1024]

    float* qkv = nullptr;
    float* attn = nullptr;
    cudaGetSymbolAddress((void**)&qkv, g_qkv);
    cudaGetSymbolAddress((void**)&attn, g_attn);

    // 1) QKV projection: [4096,1024] @ [1024,3072]
    {
        dim3 grid(3 * D_ / BN, M_TOK / BM);
        sgemm_kernel<<<grid, 256>>>(x, w_qkv, qkv, M_TOK, 3 * D_, D_);
    }

    // 2) Flash attention (v2)
    {
        cudaFuncSetAttribute(attn_kernel,
                             cudaFuncAttributeMaxDynamicSharedMemorySize,
                             (int)ATTN_SMEM);
        dim3 grid(S_ / 64, H_, B_);
        attn_kernel<<<grid, 256, ATTN_SMEM>>>(qkv, attn);
    }

    // 3) Output projection: [4096,1024] @ [1024,1024]
    {
        dim3 grid(D_ / BN, M_TOK / BM);
        sgemm_kernel<<<grid, 256>>>(attn, w_out, out, M_TOK, D_, D_);
    }
}